// round 4
// baseline (speedup 1.0000x reference)
#include <cuda_runtime.h>

#define NC    10
#define TPB   256
#define NBLK  1184
#define PAD   23   // words/thread: 11 sum bins + 11 cnt bins, pad so gcd(PAD,32)=1

// slots 0..9: per-class sqerr sums; slots 10..19: per-class counts
__device__ float g_partials[2 * NC * NBLK];
__device__ unsigned int g_ticket = 0;

// Per-thread smem bin update: LDS+FADD+STS, branch-free.
// Invalid pixels go to bin NC (=10); its sum and count are never read.
__device__ __forceinline__ void proc_elem(float ov, float tv, int mv, float* my)
{
    float d  = ov - tv;
    float sq = d * d;
    int cls  = (int)tv;                 // targets are exact small ints
    cls = (mv == 1) ? cls : NC;
    my[cls]      += sq;                 // sum bin
    my[11 + cls] += 1.0f;               // count bin (dummy bin absorbs invalids)
}

__global__ __launch_bounds__(TPB) void myloss2_fused_kernel(
    const float* __restrict__ o,
    const float* __restrict__ t,
    const int*   __restrict__ m,
    float* __restrict__ out,
    int n)
{
    __shared__ float bins[TPB * PAD];
    __shared__ float sh[2 * NC][TPB / 32];
    __shared__ float red[2 * NC];
    __shared__ unsigned int s_is_last;

    const int tid = threadIdx.x;
    float* my = &bins[tid * PAD];
#pragma unroll
    for (int c = 0; c < 22; c++) my[c] = 0.f;
    // bins are thread-private: no __syncthreads needed around the hot loop

    const int nvec = n >> 2;
    const float4* __restrict__ o4 = (const float4*)o;
    const float4* __restrict__ t4 = (const float4*)t;
    const int4*   __restrict__ m4 = (const int4*)m;
    const int stride = NBLK * TPB;

#pragma unroll 1
    for (int i = blockIdx.x * TPB + tid; i < nvec; i += stride) {
        float4 ov = o4[i];
        float4 tv = t4[i];
        int4   mv = m4[i];
        proc_elem(ov.x, tv.x, mv.x, my);
        proc_elem(ov.y, tv.y, mv.y, my);
        proc_elem(ov.z, tv.z, mv.z, my);
        proc_elem(ov.w, tv.w, mv.w, my);
    }

    // scalar tail (n % 4 != 0 -- not hit for this shape, kept for safety)
    if (blockIdx.x == 0 && tid == 0) {
        for (int k = (nvec << 2); k < n; k++)
            proc_elem(o[k], t[k], m[k], my);
    }

    // read back own bins
    float sum[NC], cnt[NC];
#pragma unroll
    for (int c = 0; c < NC; c++) {
        sum[c] = my[c];
        cnt[c] = my[11 + c];
    }

    // warp reduce 20 values
    const unsigned full = 0xffffffffu;
#pragma unroll
    for (int c = 0; c < NC; c++) {
#pragma unroll
        for (int off = 16; off; off >>= 1) {
            sum[c] += __shfl_down_sync(full, sum[c], off);
            cnt[c] += __shfl_down_sync(full, cnt[c], off);
        }
    }

    const int wid = tid >> 5;
    const int lid = tid & 31;
    if (lid == 0) {
#pragma unroll
        for (int c = 0; c < NC; c++) {
            sh[c][wid]      = sum[c];
            sh[NC + c][wid] = cnt[c];
        }
    }
    __syncthreads();

    if (tid < 2 * NC) {
        float a = 0.f;
#pragma unroll
        for (int w = 0; w < TPB / 32; w++) a += sh[tid][w];
        g_partials[tid * NBLK + blockIdx.x] = a;  // deterministic write
    }

    // ---- last-block-done fused finalize ----
    __threadfence();
    if (tid == 0) {
        unsigned int tk = atomicAdd(&g_ticket, 1u);
        s_is_last = (tk == (unsigned)(gridDim.x - 1)) ? 1u : 0u;
    }
    __syncthreads();
    if (!s_is_last) return;

    for (int slot = wid; slot < 2 * NC; slot += TPB / 32) {
        float a = 0.f;
        for (int b = lid; b < NBLK; b += 32)
            a += g_partials[slot * NBLK + b];
#pragma unroll
        for (int off = 16; off; off >>= 1)
            a += __shfl_down_sync(full, a, off);
        if (lid == 0) red[slot] = a;
    }
    __syncthreads();

    if (tid == 0) {
        float loss = 0.f;
#pragma unroll
        for (int c = 0; c < NC; c++) {
            float s  = red[c];
            float nn = red[NC + c];
            float le = (nn > 0.f) ? s / fmaxf(nn, 1.0f) : 0.0f;
            out[1 + c]  = le;   // loss_each
            out[11 + c] = nn;   // class_n
            loss += 0.1f * le;
        }
        out[0] = loss;
        g_ticket = 0;           // reset for next graph replay
    }
}

extern "C" void kernel_launch(void* const* d_in, const int* in_sizes, int n_in,
                              void* d_out, int out_size)
{
    const float* o = (const float*)d_in[0];
    const float* t = (const float*)d_in[1];
    const int*   m = (const int*)d_in[2];
    float* out = (float*)d_out;
    int n = in_sizes[0];

    myloss2_fused_kernel<<<NBLK, TPB>>>(o, t, m, out, n);
}